// round 1
// baseline (speedup 1.0000x reference)
#include <cuda_runtime.h>
#include <cuda_bf16.h>
#include <math.h>

// ---------------- problem constants ----------------
#define BATCH 4
#define SEQ   2048
#define CEMB  1024
#define NHEAD 16
#define HDIM  64
#define ROWS  (BATCH*SEQ)        // 8192
#define C3    (3*CEMB)           // 3072
#define C4    (4*CEMB)           // 4096

// ---------------- scratch (no cudaMalloc allowed) ----------------
__device__ float g_ln1[(size_t)ROWS*CEMB];   // ln1 out, reused for ln2 out
__device__ float g_qkv[(size_t)ROWS*C3];
__device__ float g_y  [(size_t)ROWS*CEMB];   // attention out
__device__ float g_x2 [(size_t)ROWS*CEMB];   // x + proj
__device__ float g_h  [(size_t)ROWS*C4];     // gelu(fc) out

// ---------------- layernorm: one block per row ----------------
__global__ void ln_kernel(const float* __restrict__ x, const float* __restrict__ g,
                          const float* __restrict__ b, float* __restrict__ out) {
    int row = blockIdx.x;
    int tid = threadIdx.x;                 // 256 threads, 4 floats each
    const float4 v = ((const float4*)(x + (size_t)row*CEMB))[tid];
    float s  = v.x + v.y + v.z + v.w;
    float sq = v.x*v.x + v.y*v.y + v.z*v.z + v.w*v.w;
    #pragma unroll
    for (int o = 16; o; o >>= 1) {
        s  += __shfl_xor_sync(0xffffffffu, s,  o);
        sq += __shfl_xor_sync(0xffffffffu, sq, o);
    }
    __shared__ float ss[8], sqs[8];
    if ((tid & 31) == 0) { ss[tid >> 5] = s; sqs[tid >> 5] = sq; }
    __syncthreads();
    float tot = 0.f, totq = 0.f;
    #pragma unroll
    for (int w = 0; w < 8; ++w) { tot += ss[w]; totq += sqs[w]; }
    const float mu  = tot * (1.f / CEMB);
    const float var = totq * (1.f / CEMB) - mu * mu;
    const float rstd = rsqrtf(var + 1e-5f);
    const float4 gg = ((const float4*)g)[tid];
    const float4 bb = ((const float4*)b)[tid];
    float4 r;
    r.x = (v.x - mu) * rstd * gg.x + bb.x;
    r.y = (v.y - mu) * rstd * gg.y + bb.y;
    r.z = (v.z - mu) * rstd * gg.z + bb.z;
    r.w = (v.w - mu) * rstd * gg.w + bb.w;
    ((float4*)(out + (size_t)row*CEMB))[tid] = r;
}

// ---------------- GELU (tanh approx) ----------------
__device__ __forceinline__ float gelu_t(float v) {
    float u = 0.7978845608028654f * (v + 0.044715f * v * v * v);
    return 0.5f * v * (1.f + tanhf(u));
}

// ---------------- SGEMM 128x128x16, 256 thr, 8x8/thread ----------------
// A [M,K] row-major, B [K,N] row-major, C [M,N] = A@B + bias (+gelu / +res)
// EPI: 0 = bias, 1 = bias+gelu, 2 = bias+residual
template<int EPI>
__global__ void gemm_kernel(const float* __restrict__ A, const float* __restrict__ B,
                            const float* __restrict__ bias, const float* __restrict__ res,
                            float* __restrict__ C, int M, int N, int K) {
    __shared__ float As[16][132];   // transposed A tile, padded
    __shared__ float Bs[16][132];
    const int tid = threadIdx.x;
    const int tx = tid & 15, ty = tid >> 4;
    const int row0 = blockIdx.y * 128, col0 = blockIdx.x * 128;

    float acc[8][8];
    #pragma unroll
    for (int i = 0; i < 8; ++i)
        #pragma unroll
        for (int j = 0; j < 8; ++j) acc[i][j] = 0.f;

    for (int k0 = 0; k0 < K; k0 += 16) {
        #pragma unroll
        for (int it = 0; it < 2; ++it) {
            int idx = it * 256 + tid;
            int ar = idx >> 2, ac = (idx & 3) * 4;
            float4 av = *(const float4*)(A + (size_t)(row0 + ar) * K + k0 + ac);
            As[ac + 0][ar] = av.x; As[ac + 1][ar] = av.y;
            As[ac + 2][ar] = av.z; As[ac + 3][ar] = av.w;
            int br = idx >> 5, bc = (idx & 31) * 4;
            *(float4*)(&Bs[br][bc]) = *(const float4*)(B + (size_t)(k0 + br) * N + col0 + bc);
        }
        __syncthreads();
        #pragma unroll
        for (int kk = 0; kk < 16; ++kk) {
            float a[8], b[8];
            *(float4*)(a)     = *(float4*)(&As[kk][ty * 4]);
            *(float4*)(a + 4) = *(float4*)(&As[kk][64 + ty * 4]);
            *(float4*)(b)     = *(float4*)(&Bs[kk][tx * 4]);
            *(float4*)(b + 4) = *(float4*)(&Bs[kk][64 + tx * 4]);
            #pragma unroll
            for (int i = 0; i < 8; ++i)
                #pragma unroll
                for (int j = 0; j < 8; ++j) acc[i][j] += a[i] * b[j];
        }
        __syncthreads();
    }
    // epilogue: rows {row0+ty*4+i, row0+64+ty*4+i}, cols {col0+tx*4+j, col0+64+tx*4+j}
    #pragma unroll
    for (int i = 0; i < 8; ++i) {
        int r = row0 + ((i < 4) ? (ty * 4 + i) : (64 + ty * 4 + i - 4));
        #pragma unroll
        for (int jh = 0; jh < 2; ++jh) {
            int c = col0 + jh * 64 + tx * 4;
            float4 bv = *(const float4*)(bias + c);
            float v0 = acc[i][jh * 4 + 0] + bv.x;
            float v1 = acc[i][jh * 4 + 1] + bv.y;
            float v2 = acc[i][jh * 4 + 2] + bv.z;
            float v3 = acc[i][jh * 4 + 3] + bv.w;
            if (EPI == 1) { v0 = gelu_t(v0); v1 = gelu_t(v1); v2 = gelu_t(v2); v3 = gelu_t(v3); }
            if (EPI == 2) {
                float4 rv = *(const float4*)(res + (size_t)r * N + c);
                v0 += rv.x; v1 += rv.y; v2 += rv.z; v3 += rv.w;
            }
            float4 ov; ov.x = v0; ov.y = v1; ov.z = v2; ov.w = v3;
            *(float4*)(C + (size_t)r * N + c) = ov;
        }
    }
}

// ---------------- flash attention: 64x64 tiles, causal ----------------
// qkv: [ROWS, 3C] (q cols [0,1024), k [1024,2048), v [2048,3072))
// grid: (SEQ/64, BATCH*NHEAD), 256 threads, dyn smem 50688 B
#define QPAD 65
#define VPAD 68
__global__ void attn_kernel(const float* __restrict__ qkv, float* __restrict__ y) {
    extern __shared__ float sm[];
    float* Qts = sm;                 // [64 d][65 r]
    float* KPs = sm + 64 * QPAD;     // K^T then P^T  [64][65]
    float* Vs  = sm + 2 * 64 * QPAD; // [64 c][68 d]
    const int qt = blockIdx.x, bh = blockIdx.y;
    const int b = bh >> 4, h = bh & 15;
    const int tid = threadIdx.x;
    const int tx = tid & 15, ty = tid >> 4;
    const int q0 = qt * 64;
    const size_t base = ((size_t)b * SEQ) * C3 + (size_t)h * HDIM;

    // load Q tile transposed (d-major)
    #pragma unroll
    for (int it = 0; it < 4; ++it) {
        int idx = it * 256 + tid;
        int r = idx >> 4, d0 = (idx & 15) * 4;
        float4 qv = *(const float4*)(qkv + base + (size_t)(q0 + r) * C3 + d0);
        Qts[(d0 + 0) * QPAD + r] = qv.x; Qts[(d0 + 1) * QPAD + r] = qv.y;
        Qts[(d0 + 2) * QPAD + r] = qv.z; Qts[(d0 + 3) * QPAD + r] = qv.w;
    }

    float m[4], l[4], o[4][4];
    #pragma unroll
    for (int i = 0; i < 4; ++i) {
        m[i] = -1e30f; l[i] = 0.f;
        #pragma unroll
        for (int j = 0; j < 4; ++j) o[i][j] = 0.f;
    }

    for (int kt = 0; kt <= qt; ++kt) {
        __syncthreads();
        // load K^T and V
        #pragma unroll
        for (int it = 0; it < 4; ++it) {
            int idx = it * 256 + tid;
            int r = idx >> 4, d0 = (idx & 15) * 4;
            size_t grow = base + (size_t)(kt * 64 + r) * C3;
            float4 kv = *(const float4*)(qkv + grow + CEMB + d0);
            KPs[(d0 + 0) * QPAD + r] = kv.x; KPs[(d0 + 1) * QPAD + r] = kv.y;
            KPs[(d0 + 2) * QPAD + r] = kv.z; KPs[(d0 + 3) * QPAD + r] = kv.w;
            float4 vv = *(const float4*)(qkv + grow + 2 * CEMB + d0);
            *(float4*)(Vs + r * VPAD + d0) = vv;
        }
        __syncthreads();

        // S = Q K^T (4x4 per thread)
        float s[4][4];
        #pragma unroll
        for (int i = 0; i < 4; ++i)
            #pragma unroll
            for (int j = 0; j < 4; ++j) s[i][j] = 0.f;
        #pragma unroll 8
        for (int d = 0; d < 64; ++d) {
            float qv[4], kv[4];
            #pragma unroll
            for (int i = 0; i < 4; ++i) qv[i] = Qts[d * QPAD + ty * 4 + i];
            #pragma unroll
            for (int j = 0; j < 4; ++j) kv[j] = KPs[d * QPAD + tx * 4 + j];
            #pragma unroll
            for (int i = 0; i < 4; ++i)
                #pragma unroll
                for (int j = 0; j < 4; ++j) s[i][j] += qv[i] * kv[j];
        }
        const float scale = 0.125f;   // 1/sqrt(64)
        const bool diag = (kt == qt);
        #pragma unroll
        for (int i = 0; i < 4; ++i)
            #pragma unroll
            for (int j = 0; j < 4; ++j) {
                s[i][j] *= scale;
                if (diag && (tx * 4 + j > ty * 4 + i)) s[i][j] = -1e30f;
            }

        // online softmax per row
        #pragma unroll
        for (int i = 0; i < 4; ++i) {
            float mt = fmaxf(fmaxf(s[i][0], s[i][1]), fmaxf(s[i][2], s[i][3]));
            #pragma unroll
            for (int off = 8; off; off >>= 1)
                mt = fmaxf(mt, __shfl_xor_sync(0xffffffffu, mt, off, 16));
            float mn = fmaxf(m[i], mt);
            float alpha = __expf(m[i] - mn);
            m[i] = mn;
            float rs = 0.f;
            #pragma unroll
            for (int j = 0; j < 4; ++j) {
                float p = __expf(s[i][j] - mn);
                s[i][j] = p; rs += p;
            }
            #pragma unroll
            for (int off = 8; off; off >>= 1)
                rs += __shfl_xor_sync(0xffffffffu, rs, off, 16);
            l[i] = l[i] * alpha + rs;
            #pragma unroll
            for (int j = 0; j < 4; ++j) o[i][j] *= alpha;
        }

        __syncthreads();          // done reading K
        // write P transposed: P^T[c][r]
        #pragma unroll
        for (int i = 0; i < 4; ++i)
            #pragma unroll
            for (int j = 0; j < 4; ++j)
                KPs[(tx * 4 + j) * QPAD + (ty * 4 + i)] = s[i][j];
        __syncthreads();

        // O += P V  (rows ty*4+i, dims tx*4+j)
        #pragma unroll 8
        for (int c = 0; c < 64; ++c) {
            float pv[4], vv[4];
            #pragma unroll
            for (int i = 0; i < 4; ++i) pv[i] = KPs[c * QPAD + ty * 4 + i];
            #pragma unroll
            for (int j = 0; j < 4; ++j) vv[j] = Vs[c * VPAD + tx * 4 + j];
            #pragma unroll
            for (int i = 0; i < 4; ++i)
                #pragma unroll
                for (int j = 0; j < 4; ++j) o[i][j] += pv[i] * vv[j];
        }
    }

    // write normalized output
    const size_t ybase = ((size_t)b * SEQ + q0) * CEMB + (size_t)h * HDIM;
    #pragma unroll
    for (int i = 0; i < 4; ++i) {
        float inv = 1.f / l[i];
        float4 ov;
        ov.x = o[i][0] * inv; ov.y = o[i][1] * inv;
        ov.z = o[i][2] * inv; ov.w = o[i][3] * inv;
        *(float4*)(y + ybase + (size_t)(ty * 4 + i) * CEMB + tx * 4) = ov;
    }
}

// ---------------- launch ----------------
extern "C" void kernel_launch(void* const* d_in, const int* in_sizes, int n_in,
                              void* d_out, int out_size) {
    const float* x      = (const float*)d_in[0];
    const float* ln1_g  = (const float*)d_in[1];
    const float* ln1_b  = (const float*)d_in[2];
    const float* w_attn = (const float*)d_in[3];
    const float* b_attn = (const float*)d_in[4];
    const float* w_proj = (const float*)d_in[5];
    const float* b_proj = (const float*)d_in[6];
    const float* ln2_g  = (const float*)d_in[7];
    const float* ln2_b  = (const float*)d_in[8];
    const float* w_fc   = (const float*)d_in[9];
    const float* b_fc   = (const float*)d_in[10];
    const float* w_fc2  = (const float*)d_in[11];
    const float* b_fc2  = (const float*)d_in[12];
    float* out = (float*)d_out;

    void *p;
    cudaGetSymbolAddress(&p, g_ln1); float* ln1 = (float*)p;
    cudaGetSymbolAddress(&p, g_qkv); float* qkv = (float*)p;
    cudaGetSymbolAddress(&p, g_y);   float* yat = (float*)p;
    cudaGetSymbolAddress(&p, g_x2);  float* x2  = (float*)p;
    cudaGetSymbolAddress(&p, g_h);   float* hh  = (float*)p;

    const int attn_smem = (2 * 64 * QPAD + 64 * VPAD) * 4;  // 50688
    cudaFuncSetAttribute(attn_kernel, cudaFuncAttributeMaxDynamicSharedMemorySize, attn_smem);

    // 1) ln1(x) -> ln1
    ln_kernel<<<ROWS, 256>>>(x, ln1_g, ln1_b, ln1);
    // 2) qkv = ln1 @ w_attn + b_attn
    gemm_kernel<0><<<dim3(C3 / 128, ROWS / 128), 256>>>(ln1, w_attn, b_attn, nullptr, qkv, ROWS, C3, CEMB);
    // 3) attention
    attn_kernel<<<dim3(SEQ / 64, BATCH * NHEAD), 256, attn_smem>>>(qkv, yat);
    // 4) x2 = x + yat @ w_proj + b_proj
    gemm_kernel<2><<<dim3(CEMB / 128, ROWS / 128), 256>>>(yat, w_proj, b_proj, x, x2, ROWS, CEMB, CEMB);
    // 5) ln2(x2) -> ln1 (reuse)
    ln_kernel<<<ROWS, 256>>>(x2, ln2_g, ln2_b, ln1);
    // 6) h = gelu(ln1 @ w_fc + b_fc)
    gemm_kernel<1><<<dim3(C4 / 128, ROWS / 128), 256>>>(ln1, w_fc, b_fc, nullptr, hh, ROWS, C4, CEMB);
    // 7) out = x2 + h @ w_fc2 + b_fc2
    gemm_kernel<2><<<dim3(CEMB / 128, ROWS / 128), 256>>>(hh, w_fc2, b_fc2, x2, out, ROWS, CEMB, C4);
}

// round 6
// speedup vs baseline: 1.7750x; 1.7750x over previous
#include <cuda_runtime.h>
#include <cuda_bf16.h>
#include <math.h>
#include <stdint.h>

// ---------------- problem constants ----------------
#define BATCH 4
#define SEQ   2048
#define CEMB  1024
#define NHEAD 16
#define HDIM  64
#define ROWS  (BATCH*SEQ)        // 8192
#define C3    (3*CEMB)           // 3072
#define C4    (4*CEMB)           // 4096

// ---------------- scratch (no cudaMalloc allowed) ----------------
__device__ float g_qkv[(size_t)ROWS*C3];
__device__ float g_x2 [(size_t)ROWS*CEMB];
__device__ __nv_bfloat16 g_a_hi[(size_t)ROWS*CEMB], g_a_lo[(size_t)ROWS*CEMB];
__device__ __nv_bfloat16 g_y_hi[(size_t)ROWS*CEMB], g_y_lo[(size_t)ROWS*CEMB];
__device__ __nv_bfloat16 g_h_hi[(size_t)ROWS*C4],  g_h_lo[(size_t)ROWS*C4];
__device__ __nv_bfloat16 g_wq_hi[(size_t)C3*CEMB],  g_wq_lo[(size_t)C3*CEMB];
__device__ __nv_bfloat16 g_wp_hi[(size_t)CEMB*CEMB],g_wp_lo[(size_t)CEMB*CEMB];
__device__ __nv_bfloat16 g_wf_hi[(size_t)C4*CEMB],  g_wf_lo[(size_t)C4*CEMB];
__device__ __nv_bfloat16 g_w2_hi[(size_t)CEMB*C4],  g_w2_lo[(size_t)CEMB*C4];

// ---------------- PTX helpers (family-safe only: cp.async / ldmatrix / mma.sync) ----------------
__device__ __forceinline__ uint32_t s2u(const void* p) {
    uint32_t a;
    asm("{ .reg .u64 t; cvta.to.shared.u64 t, %1; cvt.u32.u64 %0, t; }" : "=r"(a) : "l"(p));
    return a;
}
// SW128 (Swizzle<3,4,3>) — self-consistent between cp.async stores and ldmatrix loads
__device__ __forceinline__ uint32_t swz(uint32_t o) { return o ^ ((o >> 3) & 0x70); }

__device__ __forceinline__ void cp16(uint32_t s, const void* g) {
    asm volatile("cp.async.cg.shared.global [%0], [%1], 16;" :: "r"(s), "l"(g));
}
__device__ __forceinline__ void cp_commit() { asm volatile("cp.async.commit_group;"); }
#define CP_WAIT(N) asm volatile("cp.async.wait_group %0;" :: "n"(N))

__device__ __forceinline__ void ldsm4(uint32_t* r, uint32_t addr) {
    asm volatile("ldmatrix.sync.aligned.m8n8.x4.shared.b16 {%0,%1,%2,%3}, [%4];"
                 : "=r"(r[0]), "=r"(r[1]), "=r"(r[2]), "=r"(r[3]) : "r"(addr));
}
__device__ __forceinline__ void ldsm2(uint32_t* r, uint32_t addr) {
    asm volatile("ldmatrix.sync.aligned.m8n8.x2.shared.b16 {%0,%1}, [%2];"
                 : "=r"(r[0]), "=r"(r[1]) : "r"(addr));
}
__device__ __forceinline__ void mma16816(float* c, const uint32_t* a, const uint32_t* b) {
    asm volatile("mma.sync.aligned.m16n8k16.row.col.f32.bf16.bf16.f32 "
                 "{%0,%1,%2,%3}, {%4,%5,%6,%7}, {%8,%9}, {%0,%1,%2,%3};"
                 : "+f"(c[0]), "+f"(c[1]), "+f"(c[2]), "+f"(c[3])
                 : "r"(a[0]), "r"(a[1]), "r"(a[2]), "r"(a[3]), "r"(b[0]), "r"(b[1]));
}

// ---------------- split helpers ----------------
__device__ __forceinline__ void store_split4(__nv_bfloat16* hip, __nv_bfloat16* lop,
                                             size_t off, float v0, float v1, float v2, float v3) {
    __nv_bfloat162 h0 = __floats2bfloat162_rn(v0, v1);
    __nv_bfloat162 h1 = __floats2bfloat162_rn(v2, v3);
    float l0 = v0 - __low2float(h0),  l1 = v1 - __high2float(h0);
    float l2 = v2 - __low2float(h1),  l3 = v3 - __high2float(h1);
    *reinterpret_cast<__nv_bfloat162*>(hip + off)     = h0;
    *reinterpret_cast<__nv_bfloat162*>(hip + off + 2) = h1;
    *reinterpret_cast<__nv_bfloat162*>(lop + off)     = __floats2bfloat162_rn(l0, l1);
    *reinterpret_cast<__nv_bfloat162*>(lop + off + 2) = __floats2bfloat162_rn(l2, l3);
}
__device__ __forceinline__ void store_split2(__nv_bfloat16* hip, __nv_bfloat16* lop,
                                             size_t off, float v0, float v1) {
    __nv_bfloat162 h = __floats2bfloat162_rn(v0, v1);
    float l0 = v0 - __low2float(h), l1 = v1 - __high2float(h);
    *reinterpret_cast<__nv_bfloat162*>(hip + off) = h;
    *reinterpret_cast<__nv_bfloat162*>(lop + off) = __floats2bfloat162_rn(l0, l1);
}

// ---------------- layernorm -> bf16 hi/lo split ----------------
__global__ void ln_split_kernel(const float* __restrict__ x, const float* __restrict__ g,
                                const float* __restrict__ b,
                                __nv_bfloat16* __restrict__ ohi, __nv_bfloat16* __restrict__ olo) {
    int row = blockIdx.x;
    int tid = threadIdx.x;
    const float4 v = ((const float4*)(x + (size_t)row * CEMB))[tid];
    float s  = v.x + v.y + v.z + v.w;
    float sq = v.x * v.x + v.y * v.y + v.z * v.z + v.w * v.w;
    #pragma unroll
    for (int o = 16; o; o >>= 1) {
        s  += __shfl_xor_sync(0xffffffffu, s,  o);
        sq += __shfl_xor_sync(0xffffffffu, sq, o);
    }
    __shared__ float ss[8], sqs[8];
    if ((tid & 31) == 0) { ss[tid >> 5] = s; sqs[tid >> 5] = sq; }
    __syncthreads();
    float tot = 0.f, totq = 0.f;
    #pragma unroll
    for (int w = 0; w < 8; ++w) { tot += ss[w]; totq += sqs[w]; }
    const float mu   = tot * (1.f / CEMB);
    const float var  = totq * (1.f / CEMB) - mu * mu;
    const float rstd = rsqrtf(var + 1e-5f);
    const float4 gg = ((const float4*)g)[tid];
    const float4 bb = ((const float4*)b)[tid];
    float r0 = (v.x - mu) * rstd * gg.x + bb.x;
    float r1 = (v.y - mu) * rstd * gg.y + bb.y;
    float r2 = (v.z - mu) * rstd * gg.z + bb.z;
    float r3 = (v.w - mu) * rstd * gg.w + bb.w;
    store_split4(ohi, olo, (size_t)row * CEMB + tid * 4, r0, r1, r2, r3);
}

// ---------------- weight transpose + split: w[K,N] f32 -> [N,K] bf16 hi/lo ----------------
__global__ void wt_kernel(const float* __restrict__ w, __nv_bfloat16* __restrict__ whi,
                          __nv_bfloat16* __restrict__ wlo, int K, int N) {
    __shared__ float t[32][33];
    int n0 = blockIdx.x * 32, k0 = blockIdx.y * 32;
    int tx = threadIdx.x, ty = threadIdx.y;   // 32 x 8
    #pragma unroll
    for (int i = 0; i < 4; ++i)
        t[ty + 8 * i][tx] = w[(size_t)(k0 + ty + 8 * i) * N + n0 + tx];
    __syncthreads();
    #pragma unroll
    for (int i = 0; i < 4; ++i) {
        int r = ty + 8 * i;
        float v = t[tx][r];                    // = w[k0+tx][n0+r]
        __nv_bfloat16 h = __float2bfloat16(v);
        whi[(size_t)(n0 + r) * K + k0 + tx] = h;
        wlo[(size_t)(n0 + r) * K + k0 + tx] = __float2bfloat16(v - __bfloat162float(h));
    }
}

// ---------------- GELU (tanh approx) ----------------
__device__ __forceinline__ float gelu_t(float v) {
    float u = 0.7978845608028654f * (v + 0.044715f * v * v * v);
    return 0.5f * v * (1.f + tanhf(u));
}

// ---------------- HMMA GEMM: C[M,N] = split(A) @ split(B)^T + bias (+res / +gelu-split) ----------------
// A hi/lo: [M,K] bf16 K-major.  B hi/lo: [N,K] bf16 K-major (pre-transposed weights).
// Effective K' = 3K with thirds (A_hi,B_hi), (A_hi,B_lo), (A_lo,B_hi).
// 128x128 tile, 8 warps (2x4), warp tile 64x32, K-chunk 64, 4-stage cp.async pipeline.
#define TILE_M 128
#define TILE_N 128
#define KCH    64
#define STAGES 4
#define STG_BYTES (TILE_M * 128 + TILE_N * 128)   // 32768
#define GSMEM (STAGES * STG_BYTES)                // 131072

template<int EPI>
__global__ __launch_bounds__(256) void hmma_gemm(
    const __nv_bfloat16* __restrict__ Ahi, const __nv_bfloat16* __restrict__ Alo,
    const __nv_bfloat16* __restrict__ Bhi, const __nv_bfloat16* __restrict__ Blo,
    const float* __restrict__ bias, const float* __restrict__ res,
    float* __restrict__ Cf, __nv_bfloat16* __restrict__ Chi, __nv_bfloat16* __restrict__ Clo,
    int M, int N, int K)
{
    extern __shared__ char smem[];
    const uint32_t sb = s2u(smem);
    const int tid = threadIdx.x, wid = tid >> 5, lane = tid & 31;
    const int wm = wid & 1, wn = wid >> 1;                 // 2 x 4 warp grid
    const int row0 = blockIdx.y * TILE_M, col0 = blockIdx.x * TILE_N;
    const int cpt = K / KCH, NKC = 3 * cpt;

    auto load_chunk = [&](int kc) {
        int s = kc % STAGES;
        int t = kc / cpt;
        int k0 = (kc - t * cpt) * KCH;
        const __nv_bfloat16* A = (t < 2) ? Ahi : Alo;
        const __nv_bfloat16* B = (t == 1) ? Blo : Bhi;
        uint32_t sA = sb + s * STG_BYTES;
        uint32_t sB = sA + TILE_M * 128;
        #pragma unroll
        for (int i = 0; i < 4; ++i) {
            int idx = i * 256 + tid;
            int r = idx >> 3, c = (idx & 7) * 16;          // c: byte offset in 128B row
            cp16(sA + swz(r * 128 + c), A + (size_t)(row0 + r) * K + k0 + (c >> 1));
        }
        #pragma unroll
        for (int i = 0; i < 4; ++i) {
            int idx = i * 256 + tid;
            int r = idx >> 3, c = (idx & 7) * 16;
            cp16(sB + swz(r * 128 + c), B + (size_t)(col0 + r) * K + k0 + (c >> 1));
        }
        cp_commit();
    };

    float acc[4][4][4];
    #pragma unroll
    for (int mt = 0; mt < 4; ++mt)
        #pragma unroll
        for (int nt = 0; nt < 4; ++nt)
            #pragma unroll
            for (int q = 0; q < 4; ++q) acc[mt][nt][q] = 0.f;

    for (int kc = 0; kc < STAGES - 1; ++kc) load_chunk(kc);

    // per-lane ldmatrix address components
    const int arow = (lane & 7) + ((lane >> 3) & 1) * 8;   // row within 16
    const int akof = ((lane >> 4) & 1) * 8;                // k offset 0/8 (x4 halves)
    const int brow = lane & 7;
    const int bkof = ((lane >> 3) & 1) * 8;                // k offset 0/8 (x2 halves)

    for (int kc = 0; kc < NKC; ++kc) {
        int s = kc % STAGES;
        CP_WAIT(STAGES - 2);
        __syncthreads();
        if (kc + STAGES - 1 < NKC) load_chunk(kc + STAGES - 1);
        else cp_commit();                                   // keep group accounting uniform
        uint32_t sA = sb + s * STG_BYTES;
        uint32_t sB = sA + TILE_M * 128;
        #pragma unroll
        for (int ks = 0; ks < KCH / 16; ++ks) {
            uint32_t a[4][4], b[4][2];
            #pragma unroll
            for (int mt = 0; mt < 4; ++mt) {
                uint32_t o = (uint32_t)(wm * 64 + mt * 16 + arow) * 128 + (ks * 16 + akof) * 2;
                ldsm4(a[mt], sA + swz(o));
            }
            #pragma unroll
            for (int nt = 0; nt < 4; ++nt) {
                uint32_t o = (uint32_t)(wn * 32 + nt * 8 + brow) * 128 + (ks * 16 + bkof) * 2;
                ldsm2(b[nt], sB + swz(o));
            }
            #pragma unroll
            for (int mt = 0; mt < 4; ++mt)
                #pragma unroll
                for (int nt = 0; nt < 4; ++nt)
                    mma16816(acc[mt][nt], a[mt], b[nt]);
        }
    }

    // ---------------- epilogue (register accumulators) ----------------
    const int g = lane >> 2, i2 = (lane & 3) * 2;
    #pragma unroll
    for (int mt = 0; mt < 4; ++mt) {
        #pragma unroll
        for (int nt = 0; nt < 4; ++nt) {
            int r = row0 + wm * 64 + mt * 16 + g;
            int c = col0 + wn * 32 + nt * 8 + i2;
            float2 bv = *(const float2*)(bias + c);
            #pragma unroll
            for (int half = 0; half < 2; ++half) {
                int rr = r + half * 8;
                float v0 = acc[mt][nt][half * 2 + 0] + bv.x;
                float v1 = acc[mt][nt][half * 2 + 1] + bv.y;
                if (EPI == 1) {
                    v0 = gelu_t(v0); v1 = gelu_t(v1);
                    store_split2(Chi, Clo, (size_t)rr * N + c, v0, v1);
                } else {
                    if (EPI == 2) {
                        float2 rv = *(const float2*)(res + (size_t)rr * N + c);
                        v0 += rv.x; v1 += rv.y;
                    }
                    float2 ov; ov.x = v0; ov.y = v1;
                    *(float2*)(Cf + (size_t)rr * N + c) = ov;
                }
            }
        }
    }
}

// ---------------- flash attention: 64x64 tiles, causal (fp32 SIMT), split bf16 out ----------------
#define QPAD 65
#define VPAD 68
__global__ void attn_kernel(const float* __restrict__ qkv,
                            __nv_bfloat16* __restrict__ yhi, __nv_bfloat16* __restrict__ ylo) {
    extern __shared__ float sm[];
    float* Qts = sm;
    float* KPs = sm + 64 * QPAD;
    float* Vs  = sm + 2 * 64 * QPAD;
    const int qt = blockIdx.x, bh = blockIdx.y;
    const int b = bh >> 4, h = bh & 15;
    const int tid = threadIdx.x;
    const int tx = tid & 15, ty = tid >> 4;
    const int q0 = qt * 64;
    const size_t base = ((size_t)b * SEQ) * C3 + (size_t)h * HDIM;

    #pragma unroll
    for (int it = 0; it < 4; ++it) {
        int idx = it * 256 + tid;
        int r = idx >> 4, d0 = (idx & 15) * 4;
        float4 qv = *(const float4*)(qkv + base + (size_t)(q0 + r) * C3 + d0);
        Qts[(d0 + 0) * QPAD + r] = qv.x; Qts[(d0 + 1) * QPAD + r] = qv.y;
        Qts[(d0 + 2) * QPAD + r] = qv.z; Qts[(d0 + 3) * QPAD + r] = qv.w;
    }

    float m[4], l[4], o[4][4];
    #pragma unroll
    for (int i = 0; i < 4; ++i) {
        m[i] = -1e30f; l[i] = 0.f;
        #pragma unroll
        for (int j = 0; j < 4; ++j) o[i][j] = 0.f;
    }

    for (int kt = 0; kt <= qt; ++kt) {
        __syncthreads();
        #pragma unroll
        for (int it = 0; it < 4; ++it) {
            int idx = it * 256 + tid;
            int r = idx >> 4, d0 = (idx & 15) * 4;
            size_t grow = base + (size_t)(kt * 64 + r) * C3;
            float4 kv = *(const float4*)(qkv + grow + CEMB + d0);
            KPs[(d0 + 0) * QPAD + r] = kv.x; KPs[(d0 + 1) * QPAD + r] = kv.y;
            KPs[(d0 + 2) * QPAD + r] = kv.z; KPs[(d0 + 3) * QPAD + r] = kv.w;
            float4 vv = *(const float4*)(qkv + grow + 2 * CEMB + d0);
            *(float4*)(Vs + r * VPAD + d0) = vv;
        }
        __syncthreads();

        float s[4][4];
        #pragma unroll
        for (int i = 0; i < 4; ++i)
            #pragma unroll
            for (int j = 0; j < 4; ++j) s[i][j] = 0.f;
        #pragma unroll 8
        for (int d = 0; d < 64; ++d) {
            float qv[4], kv[4];
            #pragma unroll
            for (int i = 0; i < 4; ++i) qv[i] = Qts[d * QPAD + ty * 4 + i];
            #pragma unroll
            for (int j = 0; j < 4; ++j) kv[j] = KPs[d * QPAD + tx * 4 + j];
            #pragma unroll
            for (int i = 0; i < 4; ++i)
                #pragma unroll
                for (int j = 0; j < 4; ++j) s[i][j] += qv[i] * kv[j];
        }
        const float scale = 0.125f;
        const bool diag = (kt == qt);
        #pragma unroll
        for (int i = 0; i < 4; ++i)
            #pragma unroll
            for (int j = 0; j < 4; ++j) {
                s[i][j] *= scale;
                if (diag && (tx * 4 + j > ty * 4 + i)) s[i][j] = -1e30f;
            }

        #pragma unroll
        for (int i = 0; i < 4; ++i) {
            float mt = fmaxf(fmaxf(s[i][0], s[i][1]), fmaxf(s[i][2], s[i][3]));
            #pragma unroll
            for (int off = 8; off; off >>= 1)
                mt = fmaxf(mt, __shfl_xor_sync(0xffffffffu, mt, off, 16));
            float mn = fmaxf(m[i], mt);
            float alpha = __expf(m[i] - mn);
            m[i] = mn;
            float rs = 0.f;
            #pragma unroll
            for (int j = 0; j < 4; ++j) {
                float p = __expf(s[i][j] - mn);
                s[i][j] = p; rs += p;
            }
            #pragma unroll
            for (int off = 8; off; off >>= 1)
                rs += __shfl_xor_sync(0xffffffffu, rs, off, 16);
            l[i] = l[i] * alpha + rs;
            #pragma unroll
            for (int j = 0; j < 4; ++j) o[i][j] *= alpha;
        }

        __syncthreads();
        #pragma unroll
        for (int i = 0; i < 4; ++i)
            #pragma unroll
            for (int j = 0; j < 4; ++j)
                KPs[(tx * 4 + j) * QPAD + (ty * 4 + i)] = s[i][j];
        __syncthreads();

        #pragma unroll 8
        for (int c = 0; c < 64; ++c) {
            float pv[4], vv[4];
            #pragma unroll
            for (int i = 0; i < 4; ++i) pv[i] = KPs[c * QPAD + ty * 4 + i];
            #pragma unroll
            for (int j = 0; j < 4; ++j) vv[j] = Vs[c * VPAD + tx * 4 + j];
            #pragma unroll
            for (int i = 0; i < 4; ++i)
                #pragma unroll
                for (int j = 0; j < 4; ++j) o[i][j] += pv[i] * vv[j];
        }
    }

    const size_t ybase = ((size_t)b * SEQ + q0) * CEMB + (size_t)h * HDIM;
    #pragma unroll
    for (int i = 0; i < 4; ++i) {
        float inv = 1.f / l[i];
        store_split4(yhi, ylo, ybase + (size_t)(ty * 4 + i) * CEMB + tx * 4,
                     o[i][0] * inv, o[i][1] * inv, o[i][2] * inv, o[i][3] * inv);
    }
}

// ---------------- launch ----------------
extern "C" void kernel_launch(void* const* d_in, const int* in_sizes, int n_in,
                              void* d_out, int out_size) {
    const float* x      = (const float*)d_in[0];
    const float* ln1_g  = (const float*)d_in[1];
    const float* ln1_b  = (const float*)d_in[2];
    const float* w_attn = (const float*)d_in[3];
    const float* b_attn = (const float*)d_in[4];
    const float* w_proj = (const float*)d_in[5];
    const float* b_proj = (const float*)d_in[6];
    const float* ln2_g  = (const float*)d_in[7];
    const float* ln2_b  = (const float*)d_in[8];
    const float* w_fc   = (const float*)d_in[9];
    const float* b_fc   = (const float*)d_in[10];
    const float* w_fc2  = (const float*)d_in[11];
    const float* b_fc2  = (const float*)d_in[12];
    float* out = (float*)d_out;

    void* p;
    cudaGetSymbolAddress(&p, g_qkv);  float* qkv = (float*)p;
    cudaGetSymbolAddress(&p, g_x2);   float* x2  = (float*)p;
    cudaGetSymbolAddress(&p, g_a_hi); __nv_bfloat16* ahi = (__nv_bfloat16*)p;
    cudaGetSymbolAddress(&p, g_a_lo); __nv_bfloat16* alo = (__nv_bfloat16*)p;
    cudaGetSymbolAddress(&p, g_y_hi); __nv_bfloat16* yhi = (__nv_bfloat16*)p;
    cudaGetSymbolAddress(&p, g_y_lo); __nv_bfloat16* ylo = (__nv_bfloat16*)p;
    cudaGetSymbolAddress(&p, g_h_hi); __nv_bfloat16* hhi = (__nv_bfloat16*)p;
    cudaGetSymbolAddress(&p, g_h_lo); __nv_bfloat16* hlo = (__nv_bfloat16*)p;
    cudaGetSymbolAddress(&p, g_wq_hi); __nv_bfloat16* wqh = (__nv_bfloat16*)p;
    cudaGetSymbolAddress(&p, g_wq_lo); __nv_bfloat16* wql = (__nv_bfloat16*)p;
    cudaGetSymbolAddress(&p, g_wp_hi); __nv_bfloat16* wph = (__nv_bfloat16*)p;
    cudaGetSymbolAddress(&p, g_wp_lo); __nv_bfloat16* wpl = (__nv_bfloat16*)p;
    cudaGetSymbolAddress(&p, g_wf_hi); __nv_bfloat16* wfh = (__nv_bfloat16*)p;
    cudaGetSymbolAddress(&p, g_wf_lo); __nv_bfloat16* wfl = (__nv_bfloat16*)p;
    cudaGetSymbolAddress(&p, g_w2_hi); __nv_bfloat16* w2h = (__nv_bfloat16*)p;
    cudaGetSymbolAddress(&p, g_w2_lo); __nv_bfloat16* w2l = (__nv_bfloat16*)p;

    cudaFuncSetAttribute(hmma_gemm<0>, cudaFuncAttributeMaxDynamicSharedMemorySize, GSMEM);
    cudaFuncSetAttribute(hmma_gemm<1>, cudaFuncAttributeMaxDynamicSharedMemorySize, GSMEM);
    cudaFuncSetAttribute(hmma_gemm<2>, cudaFuncAttributeMaxDynamicSharedMemorySize, GSMEM);
    const int attn_smem = (2 * 64 * QPAD + 64 * VPAD) * 4;
    cudaFuncSetAttribute(attn_kernel, cudaFuncAttributeMaxDynamicSharedMemorySize, attn_smem);

    dim3 wtb(32, 8);
    wt_kernel<<<dim3(C3 / 32,  CEMB / 32), wtb>>>(w_attn, wqh, wql, CEMB, C3);
    wt_kernel<<<dim3(CEMB / 32, CEMB / 32), wtb>>>(w_proj, wph, wpl, CEMB, CEMB);
    wt_kernel<<<dim3(C4 / 32,  CEMB / 32), wtb>>>(w_fc,   wfh, wfl, CEMB, C4);
    wt_kernel<<<dim3(CEMB / 32, C4 / 32),  wtb>>>(w_fc2,  w2h, w2l, C4,   CEMB);

    // 1) ln1(x) -> split bf16
    ln_split_kernel<<<ROWS, 256>>>(x, ln1_g, ln1_b, ahi, alo);
    // 2) qkv = ln1 @ w_attn + b_attn  (f32 out)
    hmma_gemm<0><<<dim3(C3 / TILE_N, ROWS / TILE_M), 256, GSMEM>>>(
        ahi, alo, wqh, wql, b_attn, nullptr, qkv, nullptr, nullptr, ROWS, C3, CEMB);
    // 3) attention -> split bf16 y
    attn_kernel<<<dim3(SEQ / 64, BATCH * NHEAD), 256, attn_smem>>>(qkv, yhi, ylo);
    // 4) x2 = x + y @ w_proj + b_proj
    hmma_gemm<2><<<dim3(CEMB / TILE_N, ROWS / TILE_M), 256, GSMEM>>>(
        yhi, ylo, wph, wpl, b_proj, x, x2, nullptr, nullptr, ROWS, CEMB, CEMB);
    // 5) ln2(x2) -> split bf16 (reuse a buffers)
    ln_split_kernel<<<ROWS, 256>>>(x2, ln2_g, ln2_b, ahi, alo);
    // 6) h = gelu(ln2 @ w_fc + b_fc) -> split bf16
    hmma_gemm<1><<<dim3(C4 / TILE_N, ROWS / TILE_M), 256, GSMEM>>>(
        ahi, alo, wfh, wfl, b_fc, nullptr, nullptr, hhi, hlo, ROWS, C4, CEMB);
    // 7) out = x2 + h @ w_fc2 + b_fc2
    hmma_gemm<2><<<dim3(CEMB / TILE_N, ROWS / TILE_M), 256, GSMEM>>>(
        hhi, hlo, w2h, w2l, b_fc2, x2, out, nullptr, nullptr, ROWS, CEMB, C4);
}